// round 10
// baseline (speedup 1.0000x reference)
#include <cuda_runtime.h>
#include <cuda_fp16.h>
#include <cstdint>

#define FIN   64
#define FOUT  64
#define FH    128
#define LATD  512
#define NB    16
#define HW    16384
#define KTOT  53760
#define WS    53248   // fp16 elements of packed weights per sample (single-term)

// per-sample fp16 element offsets of fragment-ordered weight buffers
#define WIN_O   0        // O=128 I=64  (8192 ele)
#define WMIDA_O 8192     // O=128 I=128 (16384)
#define WMIDB_O 24576    // O=128 I=128 (16384)
#define WOUT_O  40960    // O=64 I=128  (8192)
#define WSH_O   49152    // O=64 I=64   (4096)

__device__ __align__(16) __half g_wh[NB * WS];
__device__ __align__(16) float g_bias[NB * 512];

// ---------------- helpers ----------------
__device__ __forceinline__ uint32_t pack_f16x2(float f0, float f1) {
    uint32_t r;
    asm("cvt.rn.f16x2.f32 %0, %1, %2;" : "=r"(r) : "f"(f1), "f"(f0));
    return r;
}
__device__ __forceinline__ void split2(float f0, float f1, uint32_t& hi, uint32_t& lo) {
    asm("cvt.rn.f16x2.f32 %0, %1, %2;" : "=r"(hi) : "f"(f1), "f"(f0));
    __half2 h = *(__half2*)&hi;
    float r0 = f0 - __low2float(h), r1 = f1 - __high2float(h);
    asm("cvt.rn.f16x2.f32 %0, %1, %2;" : "=r"(lo) : "f"(r1), "f"(r0));
}

__device__ __forceinline__ void mma16816(float d[4],
    const uint32_t a[4], uint32_t b0, uint32_t b1)
{
    asm volatile(
        "mma.sync.aligned.m16n8k16.row.col.f32.f16.f16.f32 "
        "{%0,%1,%2,%3}, {%4,%5,%6,%7}, {%8,%9}, {%0,%1,%2,%3};"
        : "+f"(d[0]), "+f"(d[1]), "+f"(d[2]), "+f"(d[3])
        : "r"(a[0]), "r"(a[1]), "r"(a[2]), "r"(a[3]), "r"(b0), "r"(b1));
}

// map hypernet row k -> fragment element index / bias flag / scale
__device__ __forceinline__ int map_fel(int k, float& scale, bool& isBias) {
    const float RS128 = 0.08838834764831845f;
    const float RS64  = 0.125f;
    int o, i, I, base;
    isBias = false;
    if (k < 8192)       { o = k >> 6;            i = k & 63;  I = 64;  base = WIN_O;   scale = RS128; }
    else if (k < 24576) { int x = k - 8192;  o = x >> 7; i = x & 127; I = 128; base = WMIDA_O; scale = RS128; }
    else if (k < 40960) { int x = k - 24576; o = x >> 7; i = x & 127; I = 128; base = WMIDB_O; scale = RS128; }
    else if (k < 49152) { int x = k - 40960; o = x >> 7; i = x & 127; I = 128; base = WOUT_O;  scale = RS64; }
    else if (k < 53248) { int x = k - 49152; o = x >> 6; i = x & 63;  I = 64;  base = WSH_O;   scale = RS64; }
    else { isBias = true; scale = 1.f; return 0; }
    int KT = I / 16;
    int nt = o >> 3, kt = i >> 4;
    int tl = (o & 7) * 4 + ((i & 7) >> 1);
    int el = (((i >> 3) & 1) << 1) | (i & 1);
    return base + ((nt * KT + kt) * 32 + tl) * 4 + el;
}

// ============================================================
// Kernel A: hypernetwork GEMM on tensor cores, single-wave grid:
// 105 CTAs x 256 threads = 840 warps, one warp per 64 k-rows.
// ks[16 x 53760] = lat @ W^T, 3-term fp16 hi/lo split (fp32-accurate).
// ============================================================
__global__ __launch_bounds__(256) void hyper_kernel(
    const float* __restrict__ lat,
    const float* __restrict__ Wm,
    const float* __restrict__ bias)
{
    // A fragments (lat) hi/lo for all 32 k-chunks, fragment-ordered
    __shared__ __align__(16) uint4 sAhi[32][32];
    __shared__ __align__(16) uint4 sAlo[32][32];

    const int tid = threadIdx.x;
    for (int idx = tid; idx < 1024; idx += 256) {
        int kc = idx >> 5, ln = idx & 31;
        int r = ln >> 2, c = kc * 16 + (ln & 3) * 2;
        uint32_t h[4], l[4];
        split2(lat[r * 512 + c],           lat[r * 512 + c + 1],           h[0], l[0]);
        split2(lat[(r + 8) * 512 + c],     lat[(r + 8) * 512 + c + 1],     h[1], l[1]);
        split2(lat[r * 512 + c + 8],       lat[r * 512 + c + 9],           h[2], l[2]);
        split2(lat[(r + 8) * 512 + c + 8], lat[(r + 8) * 512 + c + 9],     h[3], l[3]);
        sAhi[kc][ln] = make_uint4(h[0], h[1], h[2], h[3]);
        sAlo[kc][ln] = make_uint4(l[0], l[1], l[2], l[3]);
    }
    __syncthreads();

    const int lane = tid & 31;
    const int g = blockIdx.x * 8 + (tid >> 5);   // 0..839
    const int kbase = g * 64;

    float acc[8][4];
#pragma unroll
    for (int t = 0; t < 8; t++) {
        acc[t][0] = 0.f; acc[t][1] = 0.f; acc[t][2] = 0.f; acc[t][3] = 0.f;
    }

    const int rrow = lane >> 2;
    const int cof  = (lane & 3) * 2;

    for (int kc = 0; kc < 32; kc++) {
        uint4 ah4 = sAhi[kc][lane];
        uint4 al4 = sAlo[kc][lane];
        uint32_t Ah[4] = {ah4.x, ah4.y, ah4.z, ah4.w};
        uint32_t Al[4] = {al4.x, al4.y, al4.z, al4.w};
#pragma unroll
        for (int t = 0; t < 8; t++) {
            const float2* wp = (const float2*)(Wm +
                (size_t)(kbase + t * 8 + rrow) * LATD + kc * 16 + cof);
            float2 w0 = wp[0];   // k, k+1
            float2 w1 = wp[4];   // k+8, k+9
            uint32_t bh0, bl0, bh1, bl1;
            split2(w0.x, w0.y, bh0, bl0);
            split2(w1.x, w1.y, bh1, bl1);
            mma16816(acc[t], Ah, bh0, bh1);
            mma16816(acc[t], Al, bh0, bh1);
            mma16816(acc[t], Ah, bl0, bl1);
        }
    }

    // epilogue: bias + scale + fp16 pack + fragment scatter
    const int s0 = lane >> 2;           // sample rows s0, s0+8
#pragma unroll
    for (int t = 0; t < 8; t++) {
#pragma unroll
        for (int j = 0; j < 2; j++) {
            int k = kbase + t * 8 + (lane & 3) * 2 + j;
            float bk = bias[k];
            float scale; bool isBias;
            int fel = map_fel(k, scale, isBias);
            float v0 = acc[t][j]     + bk;   // sample s0
            float v1 = acc[t][j + 2] + bk;   // sample s0+8
            if (isBias) {
                g_bias[s0 * 512 + (k - 53248)]       = v0;
                g_bias[(s0 + 8) * 512 + (k - 53248)] = v1;
            } else {
                g_wh[(size_t)s0 * WS + fel]       = __float2half_rn(v0 * scale);
                g_wh[(size_t)(s0 + 8) * WS + fel] = __float2half_rn(v1 * scale);
            }
        }
    }
}

// ============================================================
// Kernel B: mma.sync fused block (proven R8 structure), fp16
// single-term weights, M=32 per warp, 2-nt transient accumulators,
// per-sample grid (weights staged exactly once per CTA).
// ============================================================
template <int KT>
__device__ __forceinline__ void layer_fused(
    const uint32_t (*A0)[4], const uint32_t (*A1)[4],
    uint32_t (*N0)[4], uint32_t (*N1)[4],
    const char* __restrict__ sm, int bOff,
    const float* __restrict__ bsm, int lane, int tig)
{
#pragma unroll
    for (int c = 0; c < 8; c++) {        // chunk = 2 nt = 16 channels
        float D[2][2][4];
#pragma unroll
        for (int j = 0; j < 2; j++) {
            int nt = c * 2 + j;
            float b0 = bsm[nt * 8 + tig * 2];
            float b1 = bsm[nt * 8 + tig * 2 + 1];
#pragma unroll
            for (int m = 0; m < 2; m++) {
                D[m][j][0] = b0; D[m][j][1] = b1;
                D[m][j][2] = b0; D[m][j][3] = b1;
            }
        }
#pragma unroll
        for (int kt = 0; kt < KT; kt++) {
            uint2 bf[2];
#pragma unroll
            for (int j = 0; j < 2; j++) {
                int fo = (((c * 2 + j) * KT + kt) * 32 + lane) * 8;
                bf[j] = *(const uint2*)(sm + bOff + fo);
            }
#pragma unroll
            for (int j = 0; j < 2; j++) {
                mma16816(D[0][j], A0[kt], bf[j].x, bf[j].y);
                mma16816(D[1][j], A1[kt], bf[j].x, bf[j].y);
            }
        }
#pragma unroll
        for (int m = 0; m < 2; m++) {
            uint32_t (*N)[4] = m ? N1 : N0;
            N[c][0] = pack_f16x2(fmaxf(D[m][0][0], 0.f), fmaxf(D[m][0][1], 0.f));
            N[c][1] = pack_f16x2(fmaxf(D[m][0][2], 0.f), fmaxf(D[m][0][3], 0.f));
            N[c][2] = pack_f16x2(fmaxf(D[m][1][0], 0.f), fmaxf(D[m][1][1], 0.f));
            N[c][3] = pack_f16x2(fmaxf(D[m][1][2], 0.f), fmaxf(D[m][1][3], 0.f));
        }
    }
}

__global__ __launch_bounds__(256, 1) void conv_kernel(
    const float* __restrict__ x, float* __restrict__ out)
{
    extern __shared__ __align__(16) char smem[];
    const float* bsm = (const float*)(smem + WS * 2);

    const int tid = threadIdx.x;
    const int w = tid >> 5, lane = tid & 31;
    const int gid = lane >> 2, tig = lane & 3;
    const int b  = blockIdx.x / 9;
    const int cs = blockIdx.x % 9;

    // stage all fragment-ordered weights (106496 B) + biases (2 KB)
    {
        const uint4* src = (const uint4*)(g_wh + (size_t)b * WS);
        uint4* dst = (uint4*)smem;
        for (int i = tid; i < WS / 8; i += 256) dst[i] = src[i];
        const float4* bsrc = (const float4*)(g_bias + b * 512);
        float4* bdst = (float4*)(smem + WS * 2);
        if (tid < 128) bdst[tid] = bsrc[tid];
    }
    __syncthreads();

    const float* xb = x + (size_t)b * FIN * HW;
    float* ob = out + (size_t)b * FOUT * HW;

    uint32_t X[2][4][4];
    uint32_t Abuf[2][2][8][4];   // ping-pong [pp][half][kt][4]

    for (int t = cs; t < 64; t += 9) {
        const int base = t * 256 + w * 32;

        // ---- load x as fp16 A fragments for both m16 halves ----
#pragma unroll
        for (int m = 0; m < 2; m++) {
            const int px_lo = base + m * 16 + gid;
            const int px_hi = px_lo + 8;
#pragma unroll
            for (int kt = 0; kt < 4; kt++) {
                const float* xp = xb + (size_t)(kt * 16 + tig * 2) * HW;
                X[m][kt][0] = pack_f16x2(xp[px_lo],          xp[HW + px_lo]);
                X[m][kt][1] = pack_f16x2(xp[px_hi],          xp[HW + px_hi]);
                X[m][kt][2] = pack_f16x2(xp[8 * HW + px_lo], xp[9 * HW + px_lo]);
                X[m][kt][3] = pack_f16x2(xp[8 * HW + px_hi], xp[9 * HW + px_hi]);
            }
        }

        layer_fused<4>(X[0], X[1], Abuf[0][0], Abuf[0][1],
                       smem, WIN_O * 2, bsm + 0, lane, tig);
        layer_fused<8>(Abuf[0][0], Abuf[0][1], Abuf[1][0], Abuf[1][1],
                       smem, WMIDA_O * 2, bsm + 128, lane, tig);
        layer_fused<8>(Abuf[1][0], Abuf[1][1], Abuf[0][0], Abuf[0][1],
                       smem, WMIDB_O * 2, bsm + 256, lane, tig);

        // ---- out layer: Wout @ h + Wshort @ x ----
#pragma unroll
        for (int c = 0; c < 4; c++) {
            float D[2][2][4];
#pragma unroll
            for (int j = 0; j < 2; j++) {
                int ch = (c * 2 + j) * 8 + tig * 2;
                float b0 = bsm[384 + ch]     + bsm[448 + ch];
                float b1 = bsm[384 + ch + 1] + bsm[448 + ch + 1];
#pragma unroll
                for (int m = 0; m < 2; m++) {
                    D[m][j][0] = b0; D[m][j][1] = b1;
                    D[m][j][2] = b0; D[m][j][3] = b1;
                }
            }
#pragma unroll
            for (int kt = 0; kt < 8; kt++) {
                uint2 bf[2];
#pragma unroll
                for (int j = 0; j < 2; j++) {
                    int fo = (((c * 2 + j) * 8 + kt) * 32 + lane) * 8;
                    bf[j] = *(const uint2*)(smem + WOUT_O * 2 + fo);
                }
#pragma unroll
                for (int j = 0; j < 2; j++) {
                    mma16816(D[0][j], Abuf[0][0][kt], bf[j].x, bf[j].y);
                    mma16816(D[1][j], Abuf[0][1][kt], bf[j].x, bf[j].y);
                }
            }
#pragma unroll
            for (int kt = 0; kt < 4; kt++) {
                uint2 bf[2];
#pragma unroll
                for (int j = 0; j < 2; j++) {
                    int fo = (((c * 2 + j) * 4 + kt) * 32 + lane) * 8;
                    bf[j] = *(const uint2*)(smem + WSH_O * 2 + fo);
                }
#pragma unroll
                for (int j = 0; j < 2; j++) {
                    mma16816(D[0][j], X[0][kt], bf[j].x, bf[j].y);
                    mma16816(D[1][j], X[1][kt], bf[j].x, bf[j].y);
                }
            }
#pragma unroll
            for (int m = 0; m < 2; m++) {
                const int px_lo = base + m * 16 + gid;
                const int px_hi = px_lo + 8;
#pragma unroll
                for (int j = 0; j < 2; j++) {
                    int ch = (c * 2 + j) * 8 + tig * 2;
                    float* op = ob + (size_t)ch * HW;
                    op[px_lo]      = D[m][j][0];
                    op[HW + px_lo] = D[m][j][1];
                    op[px_hi]      = D[m][j][2];
                    op[HW + px_hi] = D[m][j][3];
                }
            }
        }
    }
}

// ============================================================
extern "C" void kernel_launch(void* const* d_in, const int* in_sizes, int n_in,
                              void* d_out, int out_size)
{
    (void)in_sizes; (void)n_in; (void)out_size;
    const float* x    = (const float*)d_in[0];
    const float* lat  = (const float*)d_in[1];
    const float* W    = (const float*)d_in[2];
    const float* bias = (const float*)d_in[3];
    float* out = (float*)d_out;

    hyper_kernel<<<105, 256>>>(lat, W, bias);

    cudaFuncSetAttribute(conv_kernel,
                         cudaFuncAttributeMaxDynamicSharedMemorySize, 110592);
    conv_kernel<<<16 * 9, 256, 110592>>>(x, out);
}

// round 11
// speedup vs baseline: 1.3464x; 1.3464x over previous
#include <cuda_runtime.h>
#include <cuda_fp16.h>
#include <cstdint>

#define FIN   64
#define FOUT  64
#define FH    128
#define LATD  512
#define NB    16
#define HW    16384
#define KTOT  53760
#define WS    53248   // fp16 elements of packed weights per sample (single-term)

// per-sample fp16 element offsets of fragment-ordered weight buffers
#define WIN_O   0        // O=128 I=64  (8192 ele)
#define WMIDA_O 8192     // O=128 I=128 (16384)
#define WMIDB_O 24576    // O=128 I=128 (16384)
#define WOUT_O  40960    // O=64 I=128  (8192)
#define WSH_O   49152    // O=64 I=64   (4096)

__device__ __align__(16) __half g_wh[NB * WS];
__device__ __align__(16) float g_bias[NB * 512];

// ---------------- helpers ----------------
__device__ __forceinline__ uint32_t pack_f16x2(float f0, float f1) {
    uint32_t r;
    asm("cvt.rn.f16x2.f32 %0, %1, %2;" : "=r"(r) : "f"(f1), "f"(f0));
    return r;
}
__device__ __forceinline__ void split2(float f0, float f1, uint32_t& hi, uint32_t& lo) {
    asm("cvt.rn.f16x2.f32 %0, %1, %2;" : "=r"(hi) : "f"(f1), "f"(f0));
    __half2 h = *(__half2*)&hi;
    float r0 = f0 - __low2float(h), r1 = f1 - __high2float(h);
    asm("cvt.rn.f16x2.f32 %0, %1, %2;" : "=r"(lo) : "f"(r1), "f"(r0));
}

__device__ __forceinline__ void mma16816(float d[4],
    const uint32_t a[4], uint32_t b0, uint32_t b1)
{
    asm volatile(
        "mma.sync.aligned.m16n8k16.row.col.f32.f16.f16.f32 "
        "{%0,%1,%2,%3}, {%4,%5,%6,%7}, {%8,%9}, {%0,%1,%2,%3};"
        : "+f"(d[0]), "+f"(d[1]), "+f"(d[2]), "+f"(d[3])
        : "r"(a[0]), "r"(a[1]), "r"(a[2]), "r"(a[3]), "r"(b0), "r"(b1));
}

// map hypernet row k -> fragment element index / bias flag / scale
__device__ __forceinline__ int map_fel(int k, float& scale, bool& isBias) {
    const float RS128 = 0.08838834764831845f;
    const float RS64  = 0.125f;
    int o, i, I, base;
    isBias = false;
    if (k < 8192)       { o = k >> 6;            i = k & 63;  I = 64;  base = WIN_O;   scale = RS128; }
    else if (k < 24576) { int x = k - 8192;  o = x >> 7; i = x & 127; I = 128; base = WMIDA_O; scale = RS128; }
    else if (k < 40960) { int x = k - 24576; o = x >> 7; i = x & 127; I = 128; base = WMIDB_O; scale = RS128; }
    else if (k < 49152) { int x = k - 40960; o = x >> 7; i = x & 127; I = 128; base = WOUT_O;  scale = RS64; }
    else if (k < 53248) { int x = k - 49152; o = x >> 6; i = x & 63;  I = 64;  base = WSH_O;   scale = RS64; }
    else { isBias = true; scale = 1.f; return 0; }
    int KT = I / 16;
    int nt = o >> 3, kt = i >> 4;
    int tl = (o & 7) * 4 + ((i & 7) >> 1);
    int el = (((i >> 3) & 1) << 1) | (i & 1);
    return base + ((nt * KT + kt) * 32 + tl) * 4 + el;
}

// ============================================================
// Kernel A: hypernetwork GEMM on tensor cores with double-buffered
// register prefetch of W (MLP ~16 -> DRAM-throughput bound).
// 105 CTAs x 256 threads; one warp per 64 k-rows, K=512.
// ============================================================
__global__ __launch_bounds__(256) void hyper_kernel(
    const float* __restrict__ lat,
    const float* __restrict__ Wm,
    const float* __restrict__ bias)
{
    // A fragments (lat) hi/lo for all 32 k-chunks, fragment-ordered
    __shared__ __align__(16) uint4 sAhi[32][32];
    __shared__ __align__(16) uint4 sAlo[32][32];

    const int tid = threadIdx.x;
    for (int idx = tid; idx < 1024; idx += 256) {
        int kc = idx >> 5, ln = idx & 31;
        int r = ln >> 2, c = kc * 16 + (ln & 3) * 2;
        uint32_t h[4], l[4];
        split2(lat[r * 512 + c],           lat[r * 512 + c + 1],           h[0], l[0]);
        split2(lat[(r + 8) * 512 + c],     lat[(r + 8) * 512 + c + 1],     h[1], l[1]);
        split2(lat[r * 512 + c + 8],       lat[r * 512 + c + 9],           h[2], l[2]);
        split2(lat[(r + 8) * 512 + c + 8], lat[(r + 8) * 512 + c + 9],     h[3], l[3]);
        sAhi[kc][ln] = make_uint4(h[0], h[1], h[2], h[3]);
        sAlo[kc][ln] = make_uint4(l[0], l[1], l[2], l[3]);
    }
    __syncthreads();

    const int lane = tid & 31;
    const int g = blockIdx.x * 8 + (tid >> 5);   // 0..839
    const int kbase = g * 64;

    float acc[8][4];
#pragma unroll
    for (int t = 0; t < 8; t++) {
        acc[t][0] = 0.f; acc[t][1] = 0.f; acc[t][2] = 0.f; acc[t][3] = 0.f;
    }

    const int rrow = lane >> 2;
    const int cof  = (lane & 3) * 2;
    // one base pointer; rows t*8 apart => +t*4096 floats; k-chunk => +16 floats
    const float* __restrict__ wb = Wm + (size_t)(kbase + rrow) * LATD + cof;

    float2 cur0[8], cur1[8], nxt0[8], nxt1[8];
#pragma unroll
    for (int t = 0; t < 8; t++) {
        cur0[t] = *(const float2*)(wb + t * 4096);
        cur1[t] = *(const float2*)(wb + t * 4096 + 8);
    }

    for (int kc = 0; kc < 32; kc++) {
        // prefetch next k-chunk (16 independent LDG.64 back-to-back)
        if (kc < 31) {
            const float* wn = wb + (kc + 1) * 16;
#pragma unroll
            for (int t = 0; t < 8; t++) {
                nxt0[t] = *(const float2*)(wn + t * 4096);
                nxt1[t] = *(const float2*)(wn + t * 4096 + 8);
            }
        }

        uint4 ah4 = sAhi[kc][lane];
        uint4 al4 = sAlo[kc][lane];
        uint32_t Ah[4] = {ah4.x, ah4.y, ah4.z, ah4.w};
        uint32_t Al[4] = {al4.x, al4.y, al4.z, al4.w};
#pragma unroll
        for (int t = 0; t < 8; t++) {
            uint32_t bh0, bl0, bh1, bl1;
            split2(cur0[t].x, cur0[t].y, bh0, bl0);
            split2(cur1[t].x, cur1[t].y, bh1, bl1);
            mma16816(acc[t], Ah, bh0, bh1);
            mma16816(acc[t], Al, bh0, bh1);
            mma16816(acc[t], Ah, bl0, bl1);
        }

#pragma unroll
        for (int t = 0; t < 8; t++) { cur0[t] = nxt0[t]; cur1[t] = nxt1[t]; }
    }

    // epilogue: bias + scale + fp16 pack + fragment scatter
    const int s0 = lane >> 2;           // sample rows s0, s0+8
#pragma unroll
    for (int t = 0; t < 8; t++) {
#pragma unroll
        for (int j = 0; j < 2; j++) {
            int k = kbase + t * 8 + (lane & 3) * 2 + j;
            float bk = bias[k];
            float scale; bool isBias;
            int fel = map_fel(k, scale, isBias);
            float v0 = acc[t][j]     + bk;   // sample s0
            float v1 = acc[t][j + 2] + bk;   // sample s0+8
            if (isBias) {
                g_bias[s0 * 512 + (k - 53248)]       = v0;
                g_bias[(s0 + 8) * 512 + (k - 53248)] = v1;
            } else {
                g_wh[(size_t)s0 * WS + fel]       = __float2half_rn(v0 * scale);
                g_wh[(size_t)(s0 + 8) * WS + fel] = __float2half_rn(v1 * scale);
            }
        }
    }
}

// ============================================================
// Kernel B: mma.sync fused block (proven R8/R10 structure), fp16
// single-term weights, M=32 per warp, 2-nt transient accumulators,
// per-sample grid (weights staged exactly once per CTA).
// ============================================================
template <int KT>
__device__ __forceinline__ void layer_fused(
    const uint32_t (*A0)[4], const uint32_t (*A1)[4],
    uint32_t (*N0)[4], uint32_t (*N1)[4],
    const char* __restrict__ sm, int bOff,
    const float* __restrict__ bsm, int lane, int tig)
{
#pragma unroll
    for (int c = 0; c < 8; c++) {        // chunk = 2 nt = 16 channels
        float D[2][2][4];
#pragma unroll
        for (int j = 0; j < 2; j++) {
            int nt = c * 2 + j;
            float b0 = bsm[nt * 8 + tig * 2];
            float b1 = bsm[nt * 8 + tig * 2 + 1];
#pragma unroll
            for (int m = 0; m < 2; m++) {
                D[m][j][0] = b0; D[m][j][1] = b1;
                D[m][j][2] = b0; D[m][j][3] = b1;
            }
        }
#pragma unroll
        for (int kt = 0; kt < KT; kt++) {
            uint2 bf[2];
#pragma unroll
            for (int j = 0; j < 2; j++) {
                int fo = (((c * 2 + j) * KT + kt) * 32 + lane) * 8;
                bf[j] = *(const uint2*)(sm + bOff + fo);
            }
#pragma unroll
            for (int j = 0; j < 2; j++) {
                mma16816(D[0][j], A0[kt], bf[j].x, bf[j].y);
                mma16816(D[1][j], A1[kt], bf[j].x, bf[j].y);
            }
        }
#pragma unroll
        for (int m = 0; m < 2; m++) {
            uint32_t (*N)[4] = m ? N1 : N0;
            N[c][0] = pack_f16x2(fmaxf(D[m][0][0], 0.f), fmaxf(D[m][0][1], 0.f));
            N[c][1] = pack_f16x2(fmaxf(D[m][0][2], 0.f), fmaxf(D[m][0][3], 0.f));
            N[c][2] = pack_f16x2(fmaxf(D[m][1][0], 0.f), fmaxf(D[m][1][1], 0.f));
            N[c][3] = pack_f16x2(fmaxf(D[m][1][2], 0.f), fmaxf(D[m][1][3], 0.f));
        }
    }
}

__global__ __launch_bounds__(256, 1) void conv_kernel(
    const float* __restrict__ x, float* __restrict__ out)
{
    extern __shared__ __align__(16) char smem[];
    const float* bsm = (const float*)(smem + WS * 2);

    const int tid = threadIdx.x;
    const int w = tid >> 5, lane = tid & 31;
    const int gid = lane >> 2, tig = lane & 3;
    const int b  = blockIdx.x / 9;
    const int cs = blockIdx.x % 9;

    // stage all fragment-ordered weights (106496 B) + biases (2 KB)
    {
        const uint4* src = (const uint4*)(g_wh + (size_t)b * WS);
        uint4* dst = (uint4*)smem;
        for (int i = tid; i < WS / 8; i += 256) dst[i] = src[i];
        const float4* bsrc = (const float4*)(g_bias + b * 512);
        float4* bdst = (float4*)(smem + WS * 2);
        if (tid < 128) bdst[tid] = bsrc[tid];
    }
    __syncthreads();

    const float* xb = x + (size_t)b * FIN * HW;
    float* ob = out + (size_t)b * FOUT * HW;

    uint32_t X[2][4][4];
    uint32_t Abuf[2][2][8][4];   // ping-pong [pp][half][kt][4]

    for (int t = cs; t < 64; t += 9) {
        const int base = t * 256 + w * 32;

        // ---- load x as fp16 A fragments for both m16 halves ----
#pragma unroll
        for (int m = 0; m < 2; m++) {
            const int px_lo = base + m * 16 + gid;
            const int px_hi = px_lo + 8;
#pragma unroll
            for (int kt = 0; kt < 4; kt++) {
                const float* xp = xb + (size_t)(kt * 16 + tig * 2) * HW;
                X[m][kt][0] = pack_f16x2(xp[px_lo],          xp[HW + px_lo]);
                X[m][kt][1] = pack_f16x2(xp[px_hi],          xp[HW + px_hi]);
                X[m][kt][2] = pack_f16x2(xp[8 * HW + px_lo], xp[9 * HW + px_lo]);
                X[m][kt][3] = pack_f16x2(xp[8 * HW + px_hi], xp[9 * HW + px_hi]);
            }
        }

        layer_fused<4>(X[0], X[1], Abuf[0][0], Abuf[0][1],
                       smem, WIN_O * 2, bsm + 0, lane, tig);
        layer_fused<8>(Abuf[0][0], Abuf[0][1], Abuf[1][0], Abuf[1][1],
                       smem, WMIDA_O * 2, bsm + 128, lane, tig);
        layer_fused<8>(Abuf[1][0], Abuf[1][1], Abuf[0][0], Abuf[0][1],
                       smem, WMIDB_O * 2, bsm + 256, lane, tig);

        // ---- out layer: Wout @ h + Wshort @ x ----
#pragma unroll
        for (int c = 0; c < 4; c++) {
            float D[2][2][4];
#pragma unroll
            for (int j = 0; j < 2; j++) {
                int ch = (c * 2 + j) * 8 + tig * 2;
                float b0 = bsm[384 + ch]     + bsm[448 + ch];
                float b1 = bsm[384 + ch + 1] + bsm[448 + ch + 1];
#pragma unroll
                for (int m = 0; m < 2; m++) {
                    D[m][j][0] = b0; D[m][j][1] = b1;
                    D[m][j][2] = b0; D[m][j][3] = b1;
                }
            }
#pragma unroll
            for (int kt = 0; kt < 8; kt++) {
                uint2 bf[2];
#pragma unroll
                for (int j = 0; j < 2; j++) {
                    int fo = (((c * 2 + j) * 8 + kt) * 32 + lane) * 8;
                    bf[j] = *(const uint2*)(smem + WOUT_O * 2 + fo);
                }
#pragma unroll
                for (int j = 0; j < 2; j++) {
                    mma16816(D[0][j], Abuf[0][0][kt], bf[j].x, bf[j].y);
                    mma16816(D[1][j], Abuf[0][1][kt], bf[j].x, bf[j].y);
                }
            }
#pragma unroll
            for (int kt = 0; kt < 4; kt++) {
                uint2 bf[2];
#pragma unroll
                for (int j = 0; j < 2; j++) {
                    int fo = (((c * 2 + j) * 4 + kt) * 32 + lane) * 8;
                    bf[j] = *(const uint2*)(smem + WSH_O * 2 + fo);
                }
#pragma unroll
                for (int j = 0; j < 2; j++) {
                    mma16816(D[0][j], X[0][kt], bf[j].x, bf[j].y);
                    mma16816(D[1][j], X[1][kt], bf[j].x, bf[j].y);
                }
            }
#pragma unroll
            for (int m = 0; m < 2; m++) {
                const int px_lo = base + m * 16 + gid;
                const int px_hi = px_lo + 8;
#pragma unroll
                for (int j = 0; j < 2; j++) {
                    int ch = (c * 2 + j) * 8 + tig * 2;
                    float* op = ob + (size_t)ch * HW;
                    op[px_lo]      = D[m][j][0];
                    op[HW + px_lo] = D[m][j][1];
                    op[px_hi]      = D[m][j][2];
                    op[HW + px_hi] = D[m][j][3];
                }
            }
        }
    }
}

// ============================================================
extern "C" void kernel_launch(void* const* d_in, const int* in_sizes, int n_in,
                              void* d_out, int out_size)
{
    (void)in_sizes; (void)n_in; (void)out_size;
    const float* x    = (const float*)d_in[0];
    const float* lat  = (const float*)d_in[1];
    const float* W    = (const float*)d_in[2];
    const float* bias = (const float*)d_in[3];
    float* out = (float*)d_out;

    hyper_kernel<<<105, 256>>>(lat, W, bias);

    cudaFuncSetAttribute(conv_kernel,
                         cudaFuncAttributeMaxDynamicSharedMemorySize, 110592);
    conv_kernel<<<16 * 9, 256, 110592>>>(x, out);
}

// round 12
// speedup vs baseline: 1.3900x; 1.0324x over previous
#include <cuda_runtime.h>
#include <cuda_fp16.h>
#include <cstdint>

#define FIN   64
#define FOUT  64
#define FH    128
#define LATD  512
#define NB    16
#define HW    16384
#define KTOT  53760
#define WS    53248   // fp16 elements of packed weights per sample (single-term)

// per-sample fp16 element offsets of fragment-ordered weight buffers
#define WIN_O   0        // O=128 I=64  (8192 ele)
#define WMIDA_O 8192     // O=128 I=128 (16384)
#define WMIDB_O 24576    // O=128 I=128 (16384)
#define WOUT_O  40960    // O=64 I=128  (8192)
#define WSH_O   49152    // O=64 I=64   (4096)

__device__ __align__(16) __half g_wh[NB * WS];
__device__ __align__(16) float g_bias[NB * 512];

// ---------------- helpers ----------------
__device__ __forceinline__ uint32_t pack_f16x2(float f0, float f1) {
    uint32_t r;
    asm("cvt.rn.f16x2.f32 %0, %1, %2;" : "=r"(r) : "f"(f1), "f"(f0));
    return r;
}
__device__ __forceinline__ void split2(float f0, float f1, uint32_t& hi, uint32_t& lo) {
    asm("cvt.rn.f16x2.f32 %0, %1, %2;" : "=r"(hi) : "f"(f1), "f"(f0));
    __half2 h = *(__half2*)&hi;
    float r0 = f0 - __low2float(h), r1 = f1 - __high2float(h);
    asm("cvt.rn.f16x2.f32 %0, %1, %2;" : "=r"(lo) : "f"(r1), "f"(r0));
}

__device__ __forceinline__ void mma16816(float d[4],
    const uint32_t a[4], uint32_t b0, uint32_t b1)
{
    asm volatile(
        "mma.sync.aligned.m16n8k16.row.col.f32.f16.f16.f32 "
        "{%0,%1,%2,%3}, {%4,%5,%6,%7}, {%8,%9}, {%0,%1,%2,%3};"
        : "+f"(d[0]), "+f"(d[1]), "+f"(d[2]), "+f"(d[3])
        : "r"(a[0]), "r"(a[1]), "r"(a[2]), "r"(a[3]), "r"(b0), "r"(b1));
}

// map hypernet row k -> fragment element index / bias flag / scale
__device__ __forceinline__ int map_fel(int k, float& scale, bool& isBias) {
    const float RS128 = 0.08838834764831845f;
    const float RS64  = 0.125f;
    int o, i, I, base;
    isBias = false;
    if (k < 8192)       { o = k >> 6;            i = k & 63;  I = 64;  base = WIN_O;   scale = RS128; }
    else if (k < 24576) { int x = k - 8192;  o = x >> 7; i = x & 127; I = 128; base = WMIDA_O; scale = RS128; }
    else if (k < 40960) { int x = k - 24576; o = x >> 7; i = x & 127; I = 128; base = WMIDB_O; scale = RS128; }
    else if (k < 49152) { int x = k - 40960; o = x >> 7; i = x & 127; I = 128; base = WOUT_O;  scale = RS64; }
    else if (k < 53248) { int x = k - 49152; o = x >> 6; i = x & 63;  I = 64;  base = WSH_O;   scale = RS64; }
    else { isBias = true; scale = 1.f; return 0; }
    int KT = I / 16;
    int nt = o >> 3, kt = i >> 4;
    int tl = (o & 7) * 4 + ((i & 7) >> 1);
    int el = (((i >> 3) & 1) << 1) | (i & 1);
    return base + ((nt * KT + kt) * 32 + tl) * 4 + el;
}

// ============================================================
// Kernel A: hypernetwork GEMM on tensor cores. 140 CTAs x 192 thr
// = 840 warps (one per 64 k-rows). Depth-2 k-chunk prefetch via 4
// named register buffers -> 32 LDG.64 in flight per warp.
// ============================================================
__global__ __launch_bounds__(192) void hyper_kernel(
    const float* __restrict__ lat,
    const float* __restrict__ Wm,
    const float* __restrict__ bias)
{
    __shared__ __align__(16) uint4 sAhi[32][32];
    __shared__ __align__(16) uint4 sAlo[32][32];

    const int tid = threadIdx.x;
    for (int idx = tid; idx < 1024; idx += 192) {
        int kc = idx >> 5, ln = idx & 31;
        int r = ln >> 2, c = kc * 16 + (ln & 3) * 2;
        uint32_t h[4], l[4];
        split2(lat[r * 512 + c],           lat[r * 512 + c + 1],           h[0], l[0]);
        split2(lat[(r + 8) * 512 + c],     lat[(r + 8) * 512 + c + 1],     h[1], l[1]);
        split2(lat[r * 512 + c + 8],       lat[r * 512 + c + 9],           h[2], l[2]);
        split2(lat[(r + 8) * 512 + c + 8], lat[(r + 8) * 512 + c + 9],     h[3], l[3]);
        sAhi[kc][ln] = make_uint4(h[0], h[1], h[2], h[3]);
        sAlo[kc][ln] = make_uint4(l[0], l[1], l[2], l[3]);
    }
    __syncthreads();

    const int lane = tid & 31;
    const int g = blockIdx.x * 6 + (tid >> 5);   // 0..839
    const int kbase = g * 64;

    float acc[8][4];
#pragma unroll
    for (int t = 0; t < 8; t++) {
        acc[t][0] = 0.f; acc[t][1] = 0.f; acc[t][2] = 0.f; acc[t][3] = 0.f;
    }

    const int rrow = lane >> 2;
    const int cof  = (lane & 3) * 2;
    const float* __restrict__ wb = Wm + (size_t)(kbase + rrow) * LATD + cof;

    float2 buf0[16], buf1[16], buf2[16], buf3[16];

#define HPF(NB_, KC_) do {                                         \
        const float* _wn = wb + (KC_) * 16;                        \
        _Pragma("unroll")                                          \
        for (int t = 0; t < 8; t++) {                              \
            NB_[t * 2]     = *(const float2*)(_wn + t * 4096);     \
            NB_[t * 2 + 1] = *(const float2*)(_wn + t * 4096 + 8); \
        }                                                          \
    } while (0)

#define HCONS(CB_, KC_) do {                                       \
        uint4 ah4 = sAhi[KC_][lane];                               \
        uint4 al4 = sAlo[KC_][lane];                               \
        uint32_t Ah[4] = {ah4.x, ah4.y, ah4.z, ah4.w};             \
        uint32_t Al[4] = {al4.x, al4.y, al4.z, al4.w};             \
        _Pragma("unroll")                                          \
        for (int t = 0; t < 8; t++) {                              \
            uint32_t bh0, bl0, bh1, bl1;                           \
            split2(CB_[t * 2].x,     CB_[t * 2].y,     bh0, bl0);  \
            split2(CB_[t * 2 + 1].x, CB_[t * 2 + 1].y, bh1, bl1);  \
            mma16816(acc[t], Ah, bh0, bh1);                        \
            mma16816(acc[t], Al, bh0, bh1);                        \
            mma16816(acc[t], Ah, bl0, bl1);                        \
        }                                                          \
    } while (0)

    HPF(buf0, 0);
    HPF(buf1, 1);
#pragma unroll 1
    for (int kq = 0; kq < 32; kq += 4) {
        bool more = kq < 28;
        HPF(buf2, kq + 2);
        HCONS(buf0, kq);
        HPF(buf3, kq + 3);
        HCONS(buf1, kq + 1);
        if (more) HPF(buf0, kq + 4);
        HCONS(buf2, kq + 2);
        if (more) HPF(buf1, kq + 5);
        HCONS(buf3, kq + 3);
    }
#undef HPF
#undef HCONS

    // epilogue: bias + scale + fp16 pack + fragment scatter
    const int s0 = lane >> 2;           // sample rows s0, s0+8
#pragma unroll
    for (int t = 0; t < 8; t++) {
#pragma unroll
        for (int j = 0; j < 2; j++) {
            int k = kbase + t * 8 + (lane & 3) * 2 + j;
            float bk = bias[k];
            float scale; bool isBias;
            int fel = map_fel(k, scale, isBias);
            float v0 = acc[t][j]     + bk;   // sample s0
            float v1 = acc[t][j + 2] + bk;   // sample s0+8
            if (isBias) {
                g_bias[s0 * 512 + (k - 53248)]       = v0;
                g_bias[(s0 + 8) * 512 + (k - 53248)] = v1;
            } else {
                g_wh[(size_t)s0 * WS + fel]       = __float2half_rn(v0 * scale);
                g_wh[(size_t)(s0 + 8) * WS + fel] = __float2half_rn(v1 * scale);
            }
        }
    }
}

// ============================================================
// Kernel B: mma.sync fused block (proven R8/R10 structure), fp16
// single-term weights, M=32 per warp, 2-nt transient accumulators,
// per-sample grid (weights staged exactly once per CTA).
// ============================================================
template <int KT>
__device__ __forceinline__ void layer_fused(
    const uint32_t (*A0)[4], const uint32_t (*A1)[4],
    uint32_t (*N0)[4], uint32_t (*N1)[4],
    const char* __restrict__ sm, int bOff,
    const float* __restrict__ bsm, int lane, int tig)
{
#pragma unroll
    for (int c = 0; c < 8; c++) {        // chunk = 2 nt = 16 channels
        float D[2][2][4];
#pragma unroll
        for (int j = 0; j < 2; j++) {
            int nt = c * 2 + j;
            float b0 = bsm[nt * 8 + tig * 2];
            float b1 = bsm[nt * 8 + tig * 2 + 1];
#pragma unroll
            for (int m = 0; m < 2; m++) {
                D[m][j][0] = b0; D[m][j][1] = b1;
                D[m][j][2] = b0; D[m][j][3] = b1;
            }
        }
#pragma unroll
        for (int kt = 0; kt < KT; kt++) {
            uint2 bf[2];
#pragma unroll
            for (int j = 0; j < 2; j++) {
                int fo = (((c * 2 + j) * KT + kt) * 32 + lane) * 8;
                bf[j] = *(const uint2*)(sm + bOff + fo);
            }
#pragma unroll
            for (int j = 0; j < 2; j++) {
                mma16816(D[0][j], A0[kt], bf[j].x, bf[j].y);
                mma16816(D[1][j], A1[kt], bf[j].x, bf[j].y);
            }
        }
#pragma unroll
        for (int m = 0; m < 2; m++) {
            uint32_t (*N)[4] = m ? N1 : N0;
            N[c][0] = pack_f16x2(fmaxf(D[m][0][0], 0.f), fmaxf(D[m][0][1], 0.f));
            N[c][1] = pack_f16x2(fmaxf(D[m][0][2], 0.f), fmaxf(D[m][0][3], 0.f));
            N[c][2] = pack_f16x2(fmaxf(D[m][1][0], 0.f), fmaxf(D[m][1][1], 0.f));
            N[c][3] = pack_f16x2(fmaxf(D[m][1][2], 0.f), fmaxf(D[m][1][3], 0.f));
        }
    }
}

__global__ __launch_bounds__(256, 1) void conv_kernel(
    const float* __restrict__ x, float* __restrict__ out)
{
    extern __shared__ __align__(16) char smem[];
    const float* bsm = (const float*)(smem + WS * 2);

    const int tid = threadIdx.x;
    const int w = tid >> 5, lane = tid & 31;
    const int gid = lane >> 2, tig = lane & 3;
    const int b  = blockIdx.x / 9;
    const int cs = blockIdx.x % 9;

    // stage all fragment-ordered weights (106496 B) + biases (2 KB)
    {
        const uint4* src = (const uint4*)(g_wh + (size_t)b * WS);
        uint4* dst = (uint4*)smem;
        for (int i = tid; i < WS / 8; i += 256) dst[i] = src[i];
        const float4* bsrc = (const float4*)(g_bias + b * 512);
        float4* bdst = (float4*)(smem + WS * 2);
        if (tid < 128) bdst[tid] = bsrc[tid];
    }
    __syncthreads();

    const float* xb = x + (size_t)b * FIN * HW;
    float* ob = out + (size_t)b * FOUT * HW;

    uint32_t X[2][4][4];
    uint32_t Abuf[2][2][8][4];   // ping-pong [pp][half][kt][4]

    for (int t = cs; t < 64; t += 9) {
        const int base = t * 256 + w * 32;

        // ---- load x as fp16 A fragments for both m16 halves ----
#pragma unroll
        for (int m = 0; m < 2; m++) {
            const int px_lo = base + m * 16 + gid;
            const int px_hi = px_lo + 8;
#pragma unroll
            for (int kt = 0; kt < 4; kt++) {
                const float* xp = xb + (size_t)(kt * 16 + tig * 2) * HW;
                X[m][kt][0] = pack_f16x2(xp[px_lo],          xp[HW + px_lo]);
                X[m][kt][1] = pack_f16x2(xp[px_hi],          xp[HW + px_hi]);
                X[m][kt][2] = pack_f16x2(xp[8 * HW + px_lo], xp[9 * HW + px_lo]);
                X[m][kt][3] = pack_f16x2(xp[8 * HW + px_hi], xp[9 * HW + px_hi]);
            }
        }

        layer_fused<4>(X[0], X[1], Abuf[0][0], Abuf[0][1],
                       smem, WIN_O * 2, bsm + 0, lane, tig);
        layer_fused<8>(Abuf[0][0], Abuf[0][1], Abuf[1][0], Abuf[1][1],
                       smem, WMIDA_O * 2, bsm + 128, lane, tig);
        layer_fused<8>(Abuf[1][0], Abuf[1][1], Abuf[0][0], Abuf[0][1],
                       smem, WMIDB_O * 2, bsm + 256, lane, tig);

        // ---- out layer: Wout @ h + Wshort @ x ----
#pragma unroll
        for (int c = 0; c < 4; c++) {
            float D[2][2][4];
#pragma unroll
            for (int j = 0; j < 2; j++) {
                int ch = (c * 2 + j) * 8 + tig * 2;
                float b0 = bsm[384 + ch]     + bsm[448 + ch];
                float b1 = bsm[384 + ch + 1] + bsm[448 + ch + 1];
#pragma unroll
                for (int m = 0; m < 2; m++) {
                    D[m][j][0] = b0; D[m][j][1] = b1;
                    D[m][j][2] = b0; D[m][j][3] = b1;
                }
            }
#pragma unroll
            for (int kt = 0; kt < 8; kt++) {
                uint2 bf[2];
#pragma unroll
                for (int j = 0; j < 2; j++) {
                    int fo = (((c * 2 + j) * 8 + kt) * 32 + lane) * 8;
                    bf[j] = *(const uint2*)(smem + WOUT_O * 2 + fo);
                }
#pragma unroll
                for (int j = 0; j < 2; j++) {
                    mma16816(D[0][j], Abuf[0][0][kt], bf[j].x, bf[j].y);
                    mma16816(D[1][j], Abuf[0][1][kt], bf[j].x, bf[j].y);
                }
            }
#pragma unroll
            for (int kt = 0; kt < 4; kt++) {
                uint2 bf[2];
#pragma unroll
                for (int j = 0; j < 2; j++) {
                    int fo = (((c * 2 + j) * 4 + kt) * 32 + lane) * 8;
                    bf[j] = *(const uint2*)(smem + WSH_O * 2 + fo);
                }
#pragma unroll
                for (int j = 0; j < 2; j++) {
                    mma16816(D[0][j], X[0][kt], bf[j].x, bf[j].y);
                    mma16816(D[1][j], X[1][kt], bf[j].x, bf[j].y);
                }
            }
#pragma unroll
            for (int m = 0; m < 2; m++) {
                const int px_lo = base + m * 16 + gid;
                const int px_hi = px_lo + 8;
#pragma unroll
                for (int j = 0; j < 2; j++) {
                    int ch = (c * 2 + j) * 8 + tig * 2;
                    float* op = ob + (size_t)ch * HW;
                    op[px_lo]      = D[m][j][0];
                    op[HW + px_lo] = D[m][j][1];
                    op[px_hi]      = D[m][j][2];
                    op[HW + px_hi] = D[m][j][3];
                }
            }
        }
    }
}

// ============================================================
extern "C" void kernel_launch(void* const* d_in, const int* in_sizes, int n_in,
                              void* d_out, int out_size)
{
    (void)in_sizes; (void)n_in; (void)out_size;
    const float* x    = (const float*)d_in[0];
    const float* lat  = (const float*)d_in[1];
    const float* W    = (const float*)d_in[2];
    const float* bias = (const float*)d_in[3];
    float* out = (float*)d_out;

    hyper_kernel<<<140, 192>>>(lat, W, bias);

    cudaFuncSetAttribute(conv_kernel,
                         cudaFuncAttributeMaxDynamicSharedMemorySize, 110592);
    conv_kernel<<<16 * 9, 256, 110592>>>(x, out);
}